// round 11
// baseline (speedup 1.0000x reference)
#include <cuda_runtime.h>
#include <math.h>

#define NBINS    16384
#define DIM      1024
#define MULT     128
#define ROWLEN   (DIM * MULT)   // 131072 elements per batch row
#define NROWS    128

// ---------------------------------------------------------------------------
// XLA:CPU vectorized expf (GenerateVF32Exp, Cephes) — DO NOT TOUCH (verified
// bit-compatible with the reference in R9).
// ---------------------------------------------------------------------------
__device__ __forceinline__ float exp_ref(float xin) {
    float x = fminf(xin, 88.3762626647950f);
    x = fmaxf(x, -88.3762626647949f);
    float fx = floorf(__fmaf_rn(x, 1.44269504088896341f, 0.5f));
    x = __fmaf_rn(fx, -0.693359375f, x);
    x = __fmaf_rn(fx,  2.12194440e-4f, x);
    float z2 = __fmul_rn(x, x);
    float y = __fmaf_rn(1.9875691500E-4f, x, 1.3981999507E-3f);
    y = __fmaf_rn(y, x, 8.3334519073E-3f);
    y = __fmaf_rn(y, x, 4.1665795894E-2f);
    y = __fmaf_rn(y, x, 1.6666665459E-1f);
    y = __fmaf_rn(y, x, 5.0000001201E-1f);
    y = __fmaf_rn(y, z2, x);
    y = __fadd_rn(y, 1.0f);
    int n = (int)fx;
    float scale = __int_as_float((n + 127) << 23);
    float r = __fmul_rn(y, scale);
    return fmaxf(r, xin);
}

// Scratch (static device globals — no allocation)
__device__ float2 g_minmax[NROWS * 4];            // per (row, quarter) min/max
__device__ int    g_ph[NROWS * 2 * NBINS];        // per (row, half) partial hist

// ===========================================================================
// K1: per-quarter row min/max. Monotonicity: for sg>0, fl(m+fl(sg*e)) is
// non-decreasing in e (IEEE rounding is monotone), so the row extremes of z
// are z evaluated at the eps extremes — bitwise identical to reducing over
// all computed z, at 2 FMNMX/element.
// ===========================================================================
__global__ void __launch_bounds__(256)
k1_minmax(const float* __restrict__ z_mean, const float* __restrict__ z_var,
          const float* __restrict__ eps)
{
    __shared__ float s_ra[8], s_rb[8];
    const int row = blockIdx.x >> 2;
    const int q   = blockIdx.x & 3;
    const int t   = threadIdx.x;      // 0..255 == float4 column group
    const int lane = t & 31, warp = t >> 5;

    const float4* e4 = reinterpret_cast<const float4*>(eps + (size_t)row * ROWLEN);
    float4 emin = make_float4(INFINITY, INFINITY, INFINITY, INFINITY);
    float4 emax = make_float4(-INFINITY, -INFINITY, -INFINITY, -INFINITY);
    const int rbeg = q * 32;
    #pragma unroll 8
    for (int r = rbeg; r < rbeg + 32; r++) {
        float4 e = e4[r * 256 + t];
        emin.x = fminf(emin.x, e.x); emax.x = fmaxf(emax.x, e.x);
        emin.y = fminf(emin.y, e.y); emax.y = fmaxf(emax.y, e.y);
        emin.z = fminf(emin.z, e.z); emax.z = fmaxf(emax.z, e.z);
        emin.w = fminf(emin.w, e.w); emax.w = fmaxf(emax.w, e.w);
    }

    const float4 m4 = reinterpret_cast<const float4*>(z_mean + (size_t)row * DIM)[t];
    const float4 v4 = reinterpret_cast<const float4*>(z_var  + (size_t)row * DIM)[t];
    float4 sg;
    sg.x = exp_ref(__fmul_rn(0.5f, v4.x));
    sg.y = exp_ref(__fmul_rn(0.5f, v4.y));
    sg.z = exp_ref(__fmul_rn(0.5f, v4.z));
    sg.w = exp_ref(__fmul_rn(0.5f, v4.w));

    // z at the per-column eps extremes (separate mul+add, as the reference)
    float zn0 = __fadd_rn(m4.x, __fmul_rn(sg.x, emin.x));
    float zn1 = __fadd_rn(m4.y, __fmul_rn(sg.y, emin.y));
    float zn2 = __fadd_rn(m4.z, __fmul_rn(sg.z, emin.z));
    float zn3 = __fadd_rn(m4.w, __fmul_rn(sg.w, emin.w));
    float zx0 = __fadd_rn(m4.x, __fmul_rn(sg.x, emax.x));
    float zx1 = __fadd_rn(m4.y, __fmul_rn(sg.y, emax.y));
    float zx2 = __fadd_rn(m4.z, __fmul_rn(sg.z, emax.z));
    float zx3 = __fadd_rn(m4.w, __fmul_rn(sg.w, emax.w));
    float vmin = fminf(fminf(zn0, zn1), fminf(zn2, zn3));
    float vmax = fmaxf(fmaxf(zx0, zx1), fmaxf(zx2, zx3));

    #pragma unroll
    for (int o = 16; o; o >>= 1) {
        vmin = fminf(vmin, __shfl_xor_sync(0xffffffffu, vmin, o));
        vmax = fmaxf(vmax, __shfl_xor_sync(0xffffffffu, vmax, o));
    }
    if (lane == 0) { s_ra[warp] = vmin; s_rb[warp] = vmax; }
    __syncthreads();
    if (t == 0) {
        float a = s_ra[0], m = s_rb[0];
        #pragma unroll
        for (int w = 1; w < 8; w++) { a = fminf(a, s_ra[w]); m = fmaxf(m, s_rb[w]); }
        g_minmax[blockIdx.x] = make_float2(a, m);
    }
}

// ===========================================================================
// K2: half-row histogram into 64KB shared, then coalesced dump to g_ph.
// ===========================================================================
extern __shared__ int sh_hist[];

__global__ void __launch_bounds__(512, 3)
k2_hist(const float* __restrict__ z_mean, const float* __restrict__ z_var,
        const float* __restrict__ eps)
{
    const int row  = blockIdx.x >> 1;
    const int rank = blockIdx.x & 1;
    const int t    = threadIdx.x;          // 0..511
    const int d4   = t & 255;
    const int rh   = t >> 8;               // 0/1

    #pragma unroll
    for (int i = t; i < NBINS; i += 512) sh_hist[i] = 0;

    // Combine quarter extremes (min/max order-free), same recip chain as R9.
    float mn = INFINITY, mx = -INFINITY;
    #pragma unroll
    for (int i = 0; i < 4; i++) {
        float2 mm = g_minmax[row * 4 + i];
        mn = fminf(mn, mm.x);
        mx = fmaxf(mx, mm.y);
    }
    const float recip = __fdiv_rn(1.0f, __fsub_rn(mx, mn));

    const float4 m4 = reinterpret_cast<const float4*>(z_mean + (size_t)row * DIM)[d4];
    const float4 v4 = reinterpret_cast<const float4*>(z_var  + (size_t)row * DIM)[d4];
    float4 sg;
    sg.x = exp_ref(__fmul_rn(0.5f, v4.x));
    sg.y = exp_ref(__fmul_rn(0.5f, v4.y));
    sg.z = exp_ref(__fmul_rn(0.5f, v4.z));
    sg.w = exp_ref(__fmul_rn(0.5f, v4.w));

    const float4* e4 = reinterpret_cast<const float4*>(eps + (size_t)row * ROWLEN);
    __syncthreads();

    const int rbeg = rank * 64 + rh;
    #pragma unroll 4
    for (int r = rbeg; r < rank * 64 + 64; r += 2) {
        float4 e = e4[r * 256 + d4];
        float zz[4];
        zz[0] = __fadd_rn(m4.x, __fmul_rn(sg.x, e.x));
        zz[1] = __fadd_rn(m4.y, __fmul_rn(sg.y, e.y));
        zz[2] = __fadd_rn(m4.z, __fmul_rn(sg.z, e.z));
        zz[3] = __fadd_rn(m4.w, __fmul_rn(sg.w, e.w));
        #pragma unroll
        for (int j = 0; j < 4; j++) {
            float s  = __fmul_rn(__fsub_rn(zz[j], mn), recip);
            float a  = __fmul_rn(s, 16384.0f);
            int   ia = (int)a;
            ia = ia < 0 ? 0 : (ia > NBINS - 1 ? NBINS - 1 : ia);
            atomicAdd(&sh_hist[ia], 1);
        }
    }
    __syncthreads();

    // coalesced dump: 4096 int4 by 512 threads
    int4* dst = reinterpret_cast<int4*>(g_ph + (size_t)blockIdx.x * NBINS);
    const int4* src = reinterpret_cast<const int4*>(sh_hist);
    #pragma unroll
    for (int k = 0; k < 8; k++) dst[t + k * 512] = src[t + k * 512];
}

// ===========================================================================
// K3: merge halves, softmax over counts, gate x.
// ===========================================================================
__global__ void __launch_bounds__(1024)
k3_out(const float* __restrict__ x, float* __restrict__ out)
{
    __shared__ float s_red[32];
    __shared__ int   s_redI[32];
    __shared__ float s_sum;
    __shared__ int   s_cmax;

    const int row  = blockIdx.x;
    const int t    = threadIdx.x;
    const int lane = t & 31, warp = t >> 5;

    const int* pa = g_ph + (size_t)(row * 2) * NBINS;
    const int* pb = pa + NBINS;

    int cmax = 0;
    #pragma unroll
    for (int k = 0; k < NBINS / 1024; k++) {
        int i = t + k * 1024;
        int c = pa[i] + pb[i];
        sh_hist[i] = c;
        cmax = max(cmax, c);
    }
    #pragma unroll
    for (int o = 16; o; o >>= 1) cmax = max(cmax, __shfl_xor_sync(0xffffffffu, cmax, o));
    if (lane == 0) s_redI[warp] = cmax;
    __syncthreads();
    if (warp == 0) {
        int c = s_redI[lane];
        #pragma unroll
        for (int o = 16; o; o >>= 1) c = max(c, __shfl_xor_sync(0xffffffffu, c, o));
        if (lane == 0) s_cmax = c;
    }
    __syncthreads();
    const float fcmax = (float)s_cmax;

    float sum = 0.f;
    float* sh_f = reinterpret_cast<float*>(sh_hist);
    #pragma unroll
    for (int k = 0; k < NBINS / 1024; k++) {
        int i = t + k * 1024;
        float ev = exp_ref(__fsub_rn((float)sh_hist[i], fcmax));
        sh_f[i] = ev;
        sum += ev;
    }
    #pragma unroll
    for (int o = 16; o; o >>= 1) sum += __shfl_xor_sync(0xffffffffu, sum, o);
    if (lane == 0) s_red[warp] = sum;
    __syncthreads();
    if (warp == 0) {
        float s2 = s_red[lane];
        #pragma unroll
        for (int o = 16; o; o >>= 1) s2 += __shfl_xor_sync(0xffffffffu, s2, o);
        if (lane == 0) s_sum = s2;
    }
    __syncthreads();
    const float Z = s_sum;

    const float* xb = x   + (size_t)row * NBINS;
    float*       ob = out + (size_t)row * NBINS;
    #pragma unroll
    for (int k = 0; k < NBINS / 1024; k++) {
        int i = t + k * 1024;
        float p = __fdiv_rn(sh_f[i], Z);
        if (p < 1e-10f) p = 0.f;
        ob[i] = __fmul_rn(__fmul_rn(xb[i], p), 128.0f);
    }
}

extern "C" void kernel_launch(void* const* d_in, const int* in_sizes, int n_in,
                              void* d_out, int out_size)
{
    const float* z_mean = (const float*)d_in[0];
    const float* z_var  = (const float*)d_in[1];
    const float* x      = (const float*)d_in[2];
    const float* eps    = (const float*)d_in[3];
    float*       out    = (float*)d_out;

    static int configured = 0;
    cudaFuncSetAttribute(k2_hist, cudaFuncAttributeMaxDynamicSharedMemorySize,
                         NBINS * (int)sizeof(int));
    cudaFuncSetAttribute(k3_out, cudaFuncAttributeMaxDynamicSharedMemorySize,
                         NBINS * (int)sizeof(int));
    (void)configured;

    k1_minmax<<<NROWS * 4, 256>>>(z_mean, z_var, eps);
    k2_hist<<<NROWS * 2, 512, NBINS * sizeof(int)>>>(z_mean, z_var, eps);
    k3_out<<<NROWS, 1024, NBINS * sizeof(int)>>>(x, out);
}

// round 12
// speedup vs baseline: 1.5766x; 1.5766x over previous
#include <cuda_runtime.h>
#include <math.h>

#define NBINS    16384
#define DIM      1024
#define MULT     128
#define ROWLEN   (DIM * MULT)   // 131072 elements per batch row
#define NTHREADS 1024

// ---------------------------------------------------------------------------
// XLA:CPU vectorized expf (GenerateVF32Exp, Cephes) — verified bit-compatible
// with the reference in R9. DO NOT TOUCH.
// ---------------------------------------------------------------------------
__device__ __forceinline__ float exp_ref(float xin) {
    float x = fminf(xin, 88.3762626647950f);
    x = fmaxf(x, -88.3762626647949f);
    float fx = floorf(__fmaf_rn(x, 1.44269504088896341f, 0.5f));
    x = __fmaf_rn(fx, -0.693359375f, x);
    x = __fmaf_rn(fx,  2.12194440e-4f, x);
    float z2 = __fmul_rn(x, x);
    float y = __fmaf_rn(1.9875691500E-4f, x, 1.3981999507E-3f);
    y = __fmaf_rn(y, x, 8.3334519073E-3f);
    y = __fmaf_rn(y, x, 4.1665795894E-2f);
    y = __fmaf_rn(y, x, 1.6666665459E-1f);
    y = __fmaf_rn(y, x, 5.0000001201E-1f);
    y = __fmaf_rn(y, z2, x);
    y = __fadd_rn(y, 1.0f);
    int n = (int)fx;
    float scale = __int_as_float((n + 127) << 23);
    float r = __fmul_rn(y, scale);
    return fmaxf(r, xin);
}

// Dynamic shared: the 16384-bin histogram (64 KB)
extern __shared__ int sh_hist[];

__global__ void __launch_bounds__(NTHREADS, 1)
pd_kernel(const float* __restrict__ z_mean, const float* __restrict__ z_var,
          const float* __restrict__ x, const float* __restrict__ eps,
          float* __restrict__ out)
{
    __shared__ float s_redA[32];
    __shared__ float s_redB[32];
    __shared__ float s_mn, s_recip, s_sum;
    __shared__ int   s_redI[32];
    __shared__ int   s_cmax;

    const int b    = blockIdx.x;
    const int t    = threadIdx.x;
    const int lane = t & 31;
    const int warp = t >> 5;

    // zero the histogram up front — overlaps with pass A's load stream
    #pragma unroll
    for (int i = t; i < NBINS; i += NTHREADS) sh_hist[i] = 0;

    // Each thread owns a fixed float4 column of the dim axis: d4 = t % 256.
    const int d4 = t & 255;
    const float4* e4 = reinterpret_cast<const float4*>(eps + (size_t)b * ROWLEN);
    const int r0 = t >> 8;  // 0..3 : which group of repeat-rows this thread covers

    // ---------------- Pass A: eps min/max only ----------------
    // Monotonicity: sg > 0 and IEEE rounding is monotone, so
    // fl(m + fl(sg*e)) is non-decreasing in e. The row extremes of z are
    // therefore z evaluated at the per-column eps extremes — bitwise
    // identical to reducing over all z, at 2 FMNMX/element.
    float4 emin = make_float4(INFINITY, INFINITY, INFINITY, INFINITY);
    float4 emax = make_float4(-INFINITY, -INFINITY, -INFINITY, -INFINITY);
    #pragma unroll 8
    for (int r = r0; r < MULT; r += 4) {
        float4 e = e4[r * 256 + d4];
        emin.x = fminf(emin.x, e.x); emax.x = fmaxf(emax.x, e.x);
        emin.y = fminf(emin.y, e.y); emax.y = fmaxf(emax.y, e.y);
        emin.z = fminf(emin.z, e.z); emax.z = fmaxf(emax.z, e.z);
        emin.w = fminf(emin.w, e.w); emax.w = fmaxf(emax.w, e.w);
    }

    // sigma for this thread's 4 columns (off the startup critical path)
    const float4 m4 = reinterpret_cast<const float4*>(z_mean + (size_t)b * DIM)[d4];
    const float4 v4 = reinterpret_cast<const float4*>(z_var  + (size_t)b * DIM)[d4];
    float4 sg;
    sg.x = exp_ref(__fmul_rn(0.5f, v4.x));
    sg.y = exp_ref(__fmul_rn(0.5f, v4.y));
    sg.z = exp_ref(__fmul_rn(0.5f, v4.z));
    sg.w = exp_ref(__fmul_rn(0.5f, v4.w));

    // z at this thread's eps extremes (separate mul+add, as the reference)
    float zn0 = __fadd_rn(m4.x, __fmul_rn(sg.x, emin.x));
    float zn1 = __fadd_rn(m4.y, __fmul_rn(sg.y, emin.y));
    float zn2 = __fadd_rn(m4.z, __fmul_rn(sg.z, emin.z));
    float zn3 = __fadd_rn(m4.w, __fmul_rn(sg.w, emin.w));
    float zx0 = __fadd_rn(m4.x, __fmul_rn(sg.x, emax.x));
    float zx1 = __fadd_rn(m4.y, __fmul_rn(sg.y, emax.y));
    float zx2 = __fadd_rn(m4.z, __fmul_rn(sg.z, emax.z));
    float zx3 = __fadd_rn(m4.w, __fmul_rn(sg.w, emax.w));
    float vmin = fminf(fminf(zn0, zn1), fminf(zn2, zn3));
    float vmax = fmaxf(fmaxf(zx0, zx1), fmaxf(zx2, zx3));

    #pragma unroll
    for (int o = 16; o; o >>= 1) {
        vmin = fminf(vmin, __shfl_xor_sync(0xffffffffu, vmin, o));
        vmax = fmaxf(vmax, __shfl_xor_sync(0xffffffffu, vmax, o));
    }
    if (lane == 0) { s_redA[warp] = vmin; s_redB[warp] = vmax; }
    __syncthreads();
    if (warp == 0) {
        float a = s_redA[lane], m = s_redB[lane];
        #pragma unroll
        for (int o = 16; o; o >>= 1) {
            a = fminf(a, __shfl_xor_sync(0xffffffffu, a, o));
            m = fmaxf(m, __shfl_xor_sync(0xffffffffu, m, o));
        }
        if (lane == 0) {
            s_mn = a;
            // per-row reciprocal then per-element multiplies (verified R9)
            s_recip = __fdiv_rn(1.0f, __fsub_rn(m, a));
        }
    }
    __syncthreads();

    const float mn    = s_mn;
    const float recip = s_recip;

    // ---------------- Pass B: histogram (verified numerics) ----------------
    #pragma unroll 4
    for (int r = r0; r < MULT; r += 4) {
        float4 e = e4[r * 256 + d4];
        float zz[4];
        zz[0] = __fadd_rn(m4.x, __fmul_rn(sg.x, e.x));
        zz[1] = __fadd_rn(m4.y, __fmul_rn(sg.y, e.y));
        zz[2] = __fadd_rn(m4.z, __fmul_rn(sg.z, e.z));
        zz[3] = __fadd_rn(m4.w, __fmul_rn(sg.w, e.w));
        #pragma unroll
        for (int j = 0; j < 4; j++) {
            float s  = __fmul_rn(__fsub_rn(zz[j], mn), recip);
            float a  = __fmul_rn(s, 16384.0f);
            int   ia = (int)a;
            ia = ia < 0 ? 0 : (ia > NBINS - 1 ? NBINS - 1 : ia);
            atomicAdd(&sh_hist[ia], 1);
        }
    }
    __syncthreads();

    // ---------------- Softmax over counts ----------------
    int cmax = 0;
    #pragma unroll
    for (int i = t; i < NBINS; i += NTHREADS) cmax = max(cmax, sh_hist[i]);
    #pragma unroll
    for (int o = 16; o; o >>= 1) cmax = max(cmax, __shfl_xor_sync(0xffffffffu, cmax, o));
    if (lane == 0) s_redI[warp] = cmax;
    __syncthreads();
    if (warp == 0) {
        int c = s_redI[lane];
        #pragma unroll
        for (int o = 16; o; o >>= 1) c = max(c, __shfl_xor_sync(0xffffffffu, c, o));
        if (lane == 0) s_cmax = c;
    }
    __syncthreads();
    const float fcmax = (float)s_cmax;

    float sum = 0.f;
    float* sh_f = reinterpret_cast<float*>(sh_hist);
    #pragma unroll
    for (int k = 0; k < NBINS / NTHREADS; k++) {
        int i = t + k * NTHREADS;
        float ev = exp_ref(__fsub_rn((float)sh_hist[i], fcmax));
        sh_f[i] = ev;
        sum += ev;
    }
    #pragma unroll
    for (int o = 16; o; o >>= 1) sum += __shfl_xor_sync(0xffffffffu, sum, o);
    if (lane == 0) s_redA[warp] = sum;
    __syncthreads();
    if (warp == 0) {
        float s2 = s_redA[lane];
        #pragma unroll
        for (int o = 16; o; o >>= 1) s2 += __shfl_xor_sync(0xffffffffu, s2, o);
        if (lane == 0) s_sum = s2;
    }
    __syncthreads();
    const float Z = s_sum;

    // ---------------- Gate x and write out (float4) ----------------
    const float4* xb4 = reinterpret_cast<const float4*>(x   + (size_t)b * NBINS);
    float4*       ob4 = reinterpret_cast<float4*>      (out + (size_t)b * NBINS);
    #pragma unroll
    for (int k = 0; k < NBINS / (NTHREADS * 4); k++) {
        int i = t + k * NTHREADS;          // float4 index
        float4 xv = xb4[i];
        float4 ov;
        float p0 = __fdiv_rn(sh_f[i * 4 + 0], Z);
        float p1 = __fdiv_rn(sh_f[i * 4 + 1], Z);
        float p2 = __fdiv_rn(sh_f[i * 4 + 2], Z);
        float p3 = __fdiv_rn(sh_f[i * 4 + 3], Z);
        if (p0 < 1e-10f) p0 = 0.f;
        if (p1 < 1e-10f) p1 = 0.f;
        if (p2 < 1e-10f) p2 = 0.f;
        if (p3 < 1e-10f) p3 = 0.f;
        ov.x = __fmul_rn(__fmul_rn(xv.x, p0), 128.0f);
        ov.y = __fmul_rn(__fmul_rn(xv.y, p1), 128.0f);
        ov.z = __fmul_rn(__fmul_rn(xv.z, p2), 128.0f);
        ov.w = __fmul_rn(__fmul_rn(xv.w, p3), 128.0f);
        ob4[i] = ov;
    }
}

extern "C" void kernel_launch(void* const* d_in, const int* in_sizes, int n_in,
                              void* d_out, int out_size)
{
    const float* z_mean = (const float*)d_in[0];
    const float* z_var  = (const float*)d_in[1];
    const float* x      = (const float*)d_in[2];
    const float* eps    = (const float*)d_in[3];
    float*       out    = (float*)d_out;

    cudaFuncSetAttribute(pd_kernel, cudaFuncAttributeMaxDynamicSharedMemorySize,
                         NBINS * (int)sizeof(int));
    pd_kernel<<<128, NTHREADS, NBINS * sizeof(int)>>>(z_mean, z_var, x, eps, out);
}